// round 10
// baseline (speedup 1.0000x reference)
#include <cuda_runtime.h>
#include <cuda_bf16.h>
#include <cstdint>

#define BATCH 2048
#define EMBED 2048
#define NCLS  50257
#define EPS   0.1f

#define BM 256
#define BN 128
#define BK 64                      // 64 bf16 = 128B row (one swizzle phase)
#define NKT (EMBED / BK)           // 32
#define NCH ((NCLS + BN - 1) / BN) // 393
#define NSTAGE 4
#define A_BYTES (BM * BK * 2)      // 32768
#define B_BYTES (BN * BK * 2)      // 16384
#define STG_BYTES (A_BYTES + B_BYTES)           // 49152
#define SMEM_TOTAL (NSTAGE * STG_BYTES)         // 196608
#define NRED 16

// ---------------- device scratch ----------------
__device__ __nv_bfloat16 g_Wbf[(size_t)NCLS * EMBED];
__device__ __nv_bfloat16 g_Ebf[(size_t)BATCH * EMBED];
__device__ float g_sumexp[(size_t)NCH * BATCH];
__device__ float g_sumlog[(size_t)NCH * BATCH];
__device__ float g_SE2[(size_t)NRED * BATCH];
__device__ float g_SL2[(size_t)NRED * BATCH];
__device__ float g_labellogit[BATCH];
__device__ float g_part[8];

// ---------------- fp32 -> bf16 ----------------
__global__ void cvt_W(const float4* __restrict__ src) {
    size_t i = (size_t)blockIdx.x * blockDim.x + threadIdx.x;
    size_t n4 = (size_t)NCLS * EMBED / 4;
    if (i < n4) {
        float4 v = src[i];
        __nv_bfloat162* dst = reinterpret_cast<__nv_bfloat162*>(g_Wbf);
        dst[2 * i]     = __float22bfloat162_rn(make_float2(v.x, v.y));
        dst[2 * i + 1] = __float22bfloat162_rn(make_float2(v.z, v.w));
    }
}
__global__ void cvt_E(const float4* __restrict__ src) {
    size_t i = (size_t)blockIdx.x * blockDim.x + threadIdx.x;
    size_t n4 = (size_t)BATCH * EMBED / 4;
    if (i < n4) {
        float4 v = src[i];
        __nv_bfloat162* dst = reinterpret_cast<__nv_bfloat162*>(g_Ebf);
        dst[2 * i]     = __float22bfloat162_rn(make_float2(v.x, v.y));
        dst[2 * i + 1] = __float22bfloat162_rn(make_float2(v.z, v.w));
    }
}

// ---------------- PTX helpers ----------------
__device__ __forceinline__ void ldsm4(uint32_t* r, uint32_t addr) {
    asm volatile("ldmatrix.sync.aligned.m8n8.x4.shared.b16 {%0,%1,%2,%3}, [%4];\n"
                 : "=r"(r[0]), "=r"(r[1]), "=r"(r[2]), "=r"(r[3]) : "r"(addr));
}
__device__ __forceinline__ void mma16816(float* c, const uint32_t* a, uint32_t b0, uint32_t b1) {
    asm volatile("mma.sync.aligned.m16n8k16.row.col.f32.bf16.bf16.f32 "
                 "{%0,%1,%2,%3},{%4,%5,%6,%7},{%8,%9},{%0,%1,%2,%3};\n"
                 : "+f"(c[0]), "+f"(c[1]), "+f"(c[2]), "+f"(c[3])
                 : "r"(a[0]), "r"(a[1]), "r"(a[2]), "r"(a[3]), "r"(b0), "r"(b1));
}
__device__ __forceinline__ void cp16(uint32_t dst, const void* src) {
    asm volatile("cp.async.cg.shared.global [%0], [%1], 16;\n" :: "r"(dst), "l"(src) : "memory");
}
__device__ __forceinline__ void cp16z(uint32_t dst, const void* src, int srcBytes) {
    asm volatile("cp.async.cg.shared.global [%0], [%1], 16, %2;\n"
                 :: "r"(dst), "l"(src), "r"(srcBytes) : "memory");
}

// ---------------- fused GEMM + partial CE ----------------
__global__ __launch_bounds__(256, 1)
void gemm_ce_kernel(const int* __restrict__ labels) {
    extern __shared__ __align__(1024) char dynsm[];
    __shared__ float redSE[2][BM];
    __shared__ float redSL[2][BM];

    const int tid = threadIdx.x;
    const int rowBase = blockIdx.x * BM;   // x = rowblock (fast) -> wave shares W chunk
    const int chunk = blockIdx.y;          // y = class chunk
    const int cBase = chunk * BN;
    const int wid = tid >> 5, lane = tid & 31;
    const int warpM = wid & 3, warpN = wid >> 2;   // 4 x 2 warps -> 64x64 each

    const uint32_t smb = (uint32_t)__cvta_generic_to_shared(dynsm);
    const __nv_bfloat16* gA = g_Ebf + (size_t)rowBase * EMBED;

    auto issueStage = [&](int kt) {
        const int s = kt & (NSTAGE - 1);
        const uint32_t stA = smb + s * STG_BYTES;
        const uint32_t stB = stA + A_BYTES;
        const int kOff = kt * BK;
        #pragma unroll
        for (int i = 0; i < 8; i++) {          // A: 2048 16B chunks / 256 thr
            int idx = tid + i * 256;
            int r = idx >> 3, c = idx & 7;
            cp16(stA + r * 128 + ((c ^ (r & 7)) << 4),
                 gA + (size_t)r * EMBED + kOff + c * 8);
        }
        #pragma unroll
        for (int i = 0; i < 4; i++) {          // B: 1024 chunks
            int idx = tid + i * 256;
            int r = idx >> 3, c = idx & 7;
            int crow = cBase + r;
            int p = (crow < NCLS) ? 16 : 0;
            int cc = (crow < NCLS) ? crow : (NCLS - 1);
            cp16z(stB + r * 128 + ((c ^ (r & 7)) << 4),
                  g_Wbf + (size_t)cc * EMBED + kOff + c * 8, p);
        }
        asm volatile("cp.async.commit_group;\n" ::: "memory");
    };

    float acc[4][8][4];
    #pragma unroll
    for (int mt = 0; mt < 4; mt++)
        #pragma unroll
        for (int nt = 0; nt < 8; nt++)
            #pragma unroll
            for (int v = 0; v < 4; v++) acc[mt][nt][v] = 0.f;

    issueStage(0);
    issueStage(1);
    issueStage(2);

    #pragma unroll 1
    for (int kt = 0; kt < NKT; kt++) {
        if (kt < NKT - 3)      asm volatile("cp.async.wait_group 2;\n" ::: "memory");
        else if (kt == NKT - 3) asm volatile("cp.async.wait_group 2;\n" ::: "memory");
        else if (kt == NKT - 2) asm volatile("cp.async.wait_group 1;\n" ::: "memory");
        else                    asm volatile("cp.async.wait_group 0;\n" ::: "memory");
        __syncthreads();
        if (kt + 3 < NKT) issueStage(kt + 3);

        const int s = kt & (NSTAGE - 1);
        const uint32_t aS = smb + s * STG_BYTES;
        const uint32_t bS = aS + A_BYTES;

        #pragma unroll
        for (int kk = 0; kk < 4; kk++) {
            uint32_t afr[4][4];
            #pragma unroll
            for (int mt = 0; mt < 4; mt++) {
                int row = warpM * 64 + mt * 16 + (lane & 15);
                int kcol = kk * 2 + (lane >> 4);
                ldsm4(afr[mt], aS + row * 128 + ((kcol ^ (row & 7)) << 4));
            }
            uint32_t bfr[4][4];
            #pragma unroll
            for (int ng = 0; ng < 4; ng++) {
                int nrow = warpN * 64 + ng * 16 + ((lane >> 4) << 3) + (lane & 7);
                int kcol = kk * 2 + ((lane >> 3) & 1);
                ldsm4(bfr[ng], bS + nrow * 128 + ((kcol ^ (nrow & 7)) << 4));
            }
            #pragma unroll
            for (int mt = 0; mt < 4; mt++)
                #pragma unroll
                for (int ng = 0; ng < 4; ng++) {
                    mma16816(acc[mt][ng * 2 + 0], afr[mt], bfr[ng][0], bfr[ng][1]);
                    mma16816(acc[mt][ng * 2 + 1], afr[mt], bfr[ng][2], bfr[ng][3]);
                }
        }
    }
    __syncthreads();

    // ---------------- fused epilogue ----------------
    const int colBase = cBase + warpN * 64;
    #pragma unroll
    for (int mt = 0; mt < 4; mt++) {
        int rLoc0 = warpM * 64 + mt * 16 + (lane >> 2);
        int rLoc1 = rLoc0 + 8;
        int gr0 = rowBase + rLoc0, gr1 = rowBase + rLoc1;
        int lbl0 = labels[gr0], lbl1 = labels[gr1];
        float se0 = 0.f, sl0 = 0.f, se1 = 0.f, sl1 = 0.f;
        #pragma unroll
        for (int nt = 0; nt < 8; nt++) {
            int c0 = colBase + nt * 8 + ((lane & 3) << 1);
            int c1 = c0 + 1;
            float v00 = acc[mt][nt][0], v01 = acc[mt][nt][1];
            float v10 = acc[mt][nt][2], v11 = acc[mt][nt][3];
            if (c0 < NCLS) {
                se0 += __expf(v00); sl0 += v00;
                se1 += __expf(v10); sl1 += v10;
                if (c0 == lbl0) g_labellogit[gr0] = v00;
                if (c0 == lbl1) g_labellogit[gr1] = v10;
            }
            if (c1 < NCLS) {
                se0 += __expf(v01); sl0 += v01;
                se1 += __expf(v11); sl1 += v11;
                if (c1 == lbl0) g_labellogit[gr0] = v01;
                if (c1 == lbl1) g_labellogit[gr1] = v11;
            }
        }
        #pragma unroll
        for (int m = 1; m < 4; m <<= 1) {
            se0 += __shfl_xor_sync(0xffffffffu, se0, m);
            sl0 += __shfl_xor_sync(0xffffffffu, sl0, m);
            se1 += __shfl_xor_sync(0xffffffffu, se1, m);
            sl1 += __shfl_xor_sync(0xffffffffu, sl1, m);
        }
        if ((lane & 3) == 0) {
            redSE[warpN][rLoc0] = se0; redSL[warpN][rLoc0] = sl0;
            redSE[warpN][rLoc1] = se1; redSL[warpN][rLoc1] = sl1;
        }
    }
    __syncthreads();
    {
        float se = redSE[0][tid] + redSE[1][tid];
        float sl = redSL[0][tid] + redSL[1][tid];
        g_sumexp[(size_t)chunk * BATCH + rowBase + tid] = se;
        g_sumlog[(size_t)chunk * BATCH + rowBase + tid] = sl;
    }
}

// ---------------- reductions ----------------
__global__ void reduce1_kernel() {
    int row = blockIdx.x * 256 + threadIdx.x;
    int g = blockIdx.y;
    float S = 0.f, L = 0.f;
    for (int j = g; j < NCH; j += NRED) {
        S += g_sumexp[(size_t)j * BATCH + row];
        L += g_sumlog[(size_t)j * BATCH + row];
    }
    g_SE2[(size_t)g * BATCH + row] = S;
    g_SL2[(size_t)g * BATCH + row] = L;
}

__global__ void reduce2_kernel() {
    int row = blockIdx.x * 256 + threadIdx.x;
    float S = 0.f, L = 0.f;
    #pragma unroll
    for (int g = 0; g < NRED; g++) {
        S += g_SE2[(size_t)g * BATCH + row];
        L += g_SL2[(size_t)g * BATCH + row];
    }
    float per = logf(S) - (1.0f - EPS) * g_labellogit[row] - EPS * (L * (1.0f / (float)NCLS));
    __shared__ float sm[256];
    sm[threadIdx.x] = per;
    __syncthreads();
    for (int s = 128; s > 0; s >>= 1) {
        if (threadIdx.x < s) sm[threadIdx.x] += sm[threadIdx.x + s];
        __syncthreads();
    }
    if (threadIdx.x == 0) g_part[blockIdx.x] = sm[0];
}

__global__ void final_kernel(float* __restrict__ out) {
    if (threadIdx.x == 0) {
        float s = 0.f;
        for (int i = 0; i < 8; i++) s += g_part[i];
        out[0] = s * (1.0f / (float)BATCH);
    }
}

// ---------------- entry ----------------
extern "C" void kernel_launch(void* const* d_in, const int* in_sizes, int n_in,
                              void* d_out, int out_size) {
    const float* E = (const float*)d_in[0];
    const int* labels = (const int*)d_in[1];
    const float* W = (const float*)d_in[2];
    float* out = (float*)d_out;

    static int attr_set = 0;
    if (!attr_set) {
        cudaFuncSetAttribute(gemm_ce_kernel, cudaFuncAttributeMaxDynamicSharedMemorySize,
                             SMEM_TOTAL);
        attr_set = 1;
    }

    size_t nW4 = (size_t)NCLS * EMBED / 4;
    size_t nE4 = (size_t)BATCH * EMBED / 4;
    cvt_W<<<(unsigned)((nW4 + 255) / 256), 256>>>((const float4*)W);
    cvt_E<<<(unsigned)((nE4 + 255) / 256), 256>>>((const float4*)E);

    dim3 grid(BATCH / BM, NCH);   // 8 x 393 ; x fast -> wave shares W chunk via L2
    gemm_ce_kernel<<<grid, 256, SMEM_TOTAL>>>(labels);

    dim3 rg(BATCH / 256, NRED);
    reduce1_kernel<<<rg, 256>>>();
    reduce2_kernel<<<BATCH / 256, 256>>>();
    final_kernel<<<1, 32>>>(out);
}

// round 15
// speedup vs baseline: 1.0388x; 1.0388x over previous
#include <cuda_runtime.h>
#include <cuda_bf16.h>
#include <cstdint>

#define BATCH 2048
#define EMBED 2048
#define NCLS  50257
#define EPS   0.1f
#define WSCALE 128.0f
#define INV_WSCALE (1.0f / 128.0f)

#define BM 128
#define BN 128
#define BKB 128                     // k-bytes per stage chunk (128 fp8 elems = 128B row)
#define NKT (EMBED / BKB)           // 16
#define NCH ((NCLS + BN - 1) / BN)  // 393
#define NSTAGE 3
#define A_BYTES (BM * BKB)          // 16384
#define B_BYTES (BN * BKB)          // 16384
#define STG_BYTES (A_BYTES + B_BYTES)   // 32768
#define SMEM_TOTAL (NSTAGE * STG_BYTES) // 98304
#define NRED 16

// ---------------- device scratch ----------------
__device__ uint8_t g_Wq[(size_t)NCLS * EMBED];   // e4m3, pre-scaled by WSCALE
__device__ uint8_t g_Eq[(size_t)BATCH * EMBED];  // e4m3
__device__ float g_sumexp[(size_t)NCH * BATCH];
__device__ float g_sumlog[(size_t)NCH * BATCH];
__device__ float g_SE2[(size_t)NRED * BATCH];
__device__ float g_SL2[(size_t)NRED * BATCH];
__device__ float g_labellogit[BATCH];
__device__ float g_part[8];

// pack 4 floats -> 4 e4m3 bytes (x at byte0)
__device__ __forceinline__ uint32_t pack_e4m3x4(float x, float y, float z, float w) {
    uint32_t out;
    asm("{\n\t.reg .b16 lo, hi;\n\t"
        "cvt.rn.satfinite.e4m3x2.f32 lo, %2, %1;\n\t"
        "cvt.rn.satfinite.e4m3x2.f32 hi, %4, %3;\n\t"
        "mov.b32 %0, {lo, hi};\n\t}"
        : "=r"(out) : "f"(x), "f"(y), "f"(z), "f"(w));
    return out;
}

// ---------------- fp32 -> e4m3 ----------------
__global__ void cvt_W(const float4* __restrict__ src) {
    size_t i = (size_t)blockIdx.x * blockDim.x + threadIdx.x;
    size_t n4 = (size_t)NCLS * EMBED / 4;
    if (i < n4) {
        float4 v = src[i];
        reinterpret_cast<uint32_t*>(g_Wq)[i] =
            pack_e4m3x4(v.x * WSCALE, v.y * WSCALE, v.z * WSCALE, v.w * WSCALE);
    }
}
__global__ void cvt_E(const float4* __restrict__ src) {
    size_t i = (size_t)blockIdx.x * blockDim.x + threadIdx.x;
    size_t n4 = (size_t)BATCH * EMBED / 4;
    if (i < n4) {
        float4 v = src[i];
        reinterpret_cast<uint32_t*>(g_Eq)[i] = pack_e4m3x4(v.x, v.y, v.z, v.w);
    }
}

// ---------------- PTX helpers ----------------
__device__ __forceinline__ void ldsm4(uint32_t* r, uint32_t addr) {
    asm volatile("ldmatrix.sync.aligned.m8n8.x4.shared.b16 {%0,%1,%2,%3}, [%4];\n"
                 : "=r"(r[0]), "=r"(r[1]), "=r"(r[2]), "=r"(r[3]) : "r"(addr));
}
__device__ __forceinline__ void mma_fp8(float* c, const uint32_t* a, uint32_t b0, uint32_t b1) {
    asm volatile("mma.sync.aligned.m16n8k32.row.col.f32.e4m3.e4m3.f32 "
                 "{%0,%1,%2,%3},{%4,%5,%6,%7},{%8,%9},{%0,%1,%2,%3};\n"
                 : "+f"(c[0]), "+f"(c[1]), "+f"(c[2]), "+f"(c[3])
                 : "r"(a[0]), "r"(a[1]), "r"(a[2]), "r"(a[3]), "r"(b0), "r"(b1));
}
__device__ __forceinline__ void cp16(uint32_t dst, const void* src) {
    asm volatile("cp.async.cg.shared.global [%0], [%1], 16;\n" :: "r"(dst), "l"(src) : "memory");
}
__device__ __forceinline__ void cp16z(uint32_t dst, const void* src, int srcBytes) {
    asm volatile("cp.async.cg.shared.global [%0], [%1], 16, %2;\n"
                 :: "r"(dst), "l"(src), "r"(srcBytes) : "memory");
}

// ---------------- fused fp8 GEMM + partial CE ----------------
__global__ __launch_bounds__(256, 2)
void gemm_ce_kernel(const int* __restrict__ labels) {
    extern __shared__ __align__(1024) char dynsm[];
    __shared__ float redSE[2][BM];
    __shared__ float redSL[2][BM];

    const int tid = threadIdx.x;
    const int rowBase = blockIdx.x * BM;   // x fast -> wave shares W chunk via L2
    const int chunk = blockIdx.y;
    const int cBase = chunk * BN;
    const int wid = tid >> 5, lane = tid & 31;
    const int warpM = wid & 3, warpN = wid >> 2;   // 4 x 2 warps -> 32x64 each

    const uint32_t smb = (uint32_t)__cvta_generic_to_shared(dynsm);
    const uint8_t* gA = g_Eq + (size_t)rowBase * EMBED;

    auto issueStage = [&](int kt) {
        const int s = kt % NSTAGE;
        const uint32_t stA = smb + s * STG_BYTES;
        const uint32_t stB = stA + A_BYTES;
        const int kOff = kt * BKB;
        #pragma unroll
        for (int i = 0; i < 4; i++) {          // A: 1024 16B chunks / 256 thr
            int idx = tid + i * 256;
            int r = idx >> 3, c = idx & 7;
            cp16(stA + r * 128 + ((c ^ (r & 7)) << 4),
                 gA + (size_t)r * EMBED + kOff + c * 16);
        }
        #pragma unroll
        for (int i = 0; i < 4; i++) {          // B
            int idx = tid + i * 256;
            int r = idx >> 3, c = idx & 7;
            int crow = cBase + r;
            int p = (crow < NCLS) ? 16 : 0;
            int cc = (crow < NCLS) ? crow : (NCLS - 1);
            cp16z(stB + r * 128 + ((c ^ (r & 7)) << 4),
                  g_Wq + (size_t)cc * EMBED + kOff + c * 16, p);
        }
        asm volatile("cp.async.commit_group;\n" ::: "memory");
    };

    float acc[2][8][4];
    #pragma unroll
    for (int mt = 0; mt < 2; mt++)
        #pragma unroll
        for (int nt = 0; nt < 8; nt++)
            #pragma unroll
            for (int v = 0; v < 4; v++) acc[mt][nt][v] = 0.f;

    issueStage(0);
    issueStage(1);

    // ldmatrix lane mapping: m = lane>>3 selects matrix, r8 = lane&7 is the row.
    const int lm_m = lane >> 3, lm_r = lane & 7;

    #pragma unroll 1
    for (int kt = 0; kt < NKT; kt++) {
        if (kt < NKT - 2) asm volatile("cp.async.wait_group 1;\n" ::: "memory");
        else              asm volatile("cp.async.wait_group 0;\n" ::: "memory");
        __syncthreads();
        if (kt + 2 < NKT) issueStage(kt + 2);

        const int s = kt % NSTAGE;
        const uint32_t aS = smb + s * STG_BYTES;
        const uint32_t bS = aS + A_BYTES;

        #pragma unroll
        for (int kk = 0; kk < 4; kk++) {       // 4 x k32 per stage
            // A: two m16xk32 tiles. matrices: m0=rows0-7/k0-15, m1=rows8-15/k0-15,
            //                                  m2=rows0-7/k16-31, m3=rows8-15/k16-31
            uint32_t afr[2][4];
            #pragma unroll
            for (int mt = 0; mt < 2; mt++) {
                int row = warpM * 32 + mt * 16 + (lm_m & 1) * 8 + lm_r;
                int c16 = kk * 2 + (lm_m >> 1);
                ldsm4(afr[mt], aS + row * 128 + ((c16 ^ (row & 7)) << 4));
            }
            // B: four n16xk32 tiles. same matrix layout over n-rows.
            uint32_t bfr[4][4];
            #pragma unroll
            for (int ng = 0; ng < 4; ng++) {
                int nrow = warpN * 64 + ng * 16 + (lm_m & 1) * 8 + lm_r;
                int c16 = kk * 2 + (lm_m >> 1);
                ldsm4(bfr[ng], bS + nrow * 128 + ((c16 ^ (nrow & 7)) << 4));
            }
            #pragma unroll
            for (int mt = 0; mt < 2; mt++)
                #pragma unroll
                for (int ng = 0; ng < 4; ng++) {
                    // lower n-octet: b = {reg0, reg2}; upper: {reg1, reg3}
                    mma_fp8(acc[mt][ng * 2 + 0], afr[mt], bfr[ng][0], bfr[ng][2]);
                    mma_fp8(acc[mt][ng * 2 + 1], afr[mt], bfr[ng][1], bfr[ng][3]);
                }
        }
    }
    __syncthreads();

    // ---------------- fused epilogue (descale by 1/WSCALE) ----------------
    const int colBase = cBase + warpN * 64;
    #pragma unroll
    for (int mt = 0; mt < 2; mt++) {
        int rLoc0 = warpM * 32 + mt * 16 + (lane >> 2);
        int rLoc1 = rLoc0 + 8;
        int gr0 = rowBase + rLoc0, gr1 = rowBase + rLoc1;
        int lbl0 = labels[gr0], lbl1 = labels[gr1];
        float se0 = 0.f, sl0 = 0.f, se1 = 0.f, sl1 = 0.f;
        #pragma unroll
        for (int nt = 0; nt < 8; nt++) {
            int c0 = colBase + nt * 8 + ((lane & 3) << 1);
            int c1 = c0 + 1;
            float v00 = acc[mt][nt][0] * INV_WSCALE, v01 = acc[mt][nt][1] * INV_WSCALE;
            float v10 = acc[mt][nt][2] * INV_WSCALE, v11 = acc[mt][nt][3] * INV_WSCALE;
            if (c0 < NCLS) {
                se0 += __expf(v00); sl0 += v00;
                se1 += __expf(v10); sl1 += v10;
                if (c0 == lbl0) g_labellogit[gr0] = v00;
                if (c0 == lbl1) g_labellogit[gr1] = v10;
            }
            if (c1 < NCLS) {
                se0 += __expf(v01); sl0 += v01;
                se1 += __expf(v11); sl1 += v11;
                if (c1 == lbl0) g_labellogit[gr0] = v01;
                if (c1 == lbl1) g_labellogit[gr1] = v11;
            }
        }
        #pragma unroll
        for (int m = 1; m < 4; m <<= 1) {
            se0 += __shfl_xor_sync(0xffffffffu, se0, m);
            sl0 += __shfl_xor_sync(0xffffffffu, sl0, m);
            se1 += __shfl_xor_sync(0xffffffffu, se1, m);
            sl1 += __shfl_xor_sync(0xffffffffu, sl1, m);
        }
        if ((lane & 3) == 0) {
            redSE[warpN][rLoc0] = se0; redSL[warpN][rLoc0] = sl0;
            redSE[warpN][rLoc1] = se1; redSL[warpN][rLoc1] = sl1;
        }
    }
    __syncthreads();
    if (tid < BM) {
        float se = redSE[0][tid] + redSE[1][tid];
        float sl = redSL[0][tid] + redSL[1][tid];
        g_sumexp[(size_t)chunk * BATCH + rowBase + tid] = se;
        g_sumlog[(size_t)chunk * BATCH + rowBase + tid] = sl;
    }
}

// ---------------- reductions ----------------
__global__ void reduce1_kernel() {
    int row = blockIdx.x * 256 + threadIdx.x;
    int g = blockIdx.y;
    float S = 0.f, L = 0.f;
    for (int j = g; j < NCH; j += NRED) {
        S += g_sumexp[(size_t)j * BATCH + row];
        L += g_sumlog[(size_t)j * BATCH + row];
    }
    g_SE2[(size_t)g * BATCH + row] = S;
    g_SL2[(size_t)g * BATCH + row] = L;
}

__global__ void reduce2_kernel() {
    int row = blockIdx.x * 256 + threadIdx.x;
    float S = 0.f, L = 0.f;
    #pragma unroll
    for (int g = 0; g < NRED; g++) {
        S += g_SE2[(size_t)g * BATCH + row];
        L += g_SL2[(size_t)g * BATCH + row];
    }
    float per = logf(S) - (1.0f - EPS) * g_labellogit[row] - EPS * (L * (1.0f / (float)NCLS));
    __shared__ float sm[256];
    sm[threadIdx.x] = per;
    __syncthreads();
    for (int s = 128; s > 0; s >>= 1) {
        if (threadIdx.x < s) sm[threadIdx.x] += sm[threadIdx.x + s];
        __syncthreads();
    }
    if (threadIdx.x == 0) g_part[blockIdx.x] = sm[0];
}

__global__ void final_kernel(float* __restrict__ out) {
    if (threadIdx.x == 0) {
        float s = 0.f;
        for (int i = 0; i < 8; i++) s += g_part[i];
        out[0] = s * (1.0f / (float)BATCH);
    }
}

// ---------------- entry ----------------
extern "C" void kernel_launch(void* const* d_in, const int* in_sizes, int n_in,
                              void* d_out, int out_size) {
    const float* E = (const float*)d_in[0];
    const int* labels = (const int*)d_in[1];
    const float* W = (const float*)d_in[2];
    float* out = (float*)d_out;

    static int attr_set = 0;
    if (!attr_set) {
        cudaFuncSetAttribute(gemm_ce_kernel, cudaFuncAttributeMaxDynamicSharedMemorySize,
                             SMEM_TOTAL);
        attr_set = 1;
    }

    size_t nW4 = (size_t)NCLS * EMBED / 4;
    size_t nE4 = (size_t)BATCH * EMBED / 4;
    cvt_W<<<(unsigned)((nW4 + 255) / 256), 256>>>((const float4*)W);
    cvt_E<<<(unsigned)((nE4 + 255) / 256), 256>>>((const float4*)E);

    dim3 grid(BATCH / BM, NCH);   // 16 x 393
    gemm_ce_kernel<<<grid, 256, SMEM_TOTAL>>>(labels);

    dim3 rg(BATCH / 256, NRED);
    reduce1_kernel<<<rg, 256>>>();
    reduce2_kernel<<<BATCH / 256, 256>>>();
    final_kernel<<<1, 32>>>(out);
}

// round 16
// speedup vs baseline: 1.0684x; 1.0286x over previous
#include <cuda_runtime.h>
#include <cuda_bf16.h>
#include <cstdint>

#define BATCH 2048
#define EMBED 2048
#define NCLS  50257
#define EPS   0.1f

#define BM 128
#define BN 128
#define BK 64                      // 64 bf16 = 128B row
#define NKT 32                     // k-steps per tile (EMBED/BK)
#define NCH ((NCLS + BN - 1) / BN) // 393
#define NROWB (BATCH / BM)         // 16
#define NTILES (NROWB * NCH)       // 6288
#define NCTA 296                   // 148 SMs x occ2, exact
#define NSTAGE 3
#define A_BYTES (BM * BK * 2)      // 16384
#define B_BYTES (BN * BK * 2)      // 16384
#define STG_BYTES (A_BYTES + B_BYTES)   // 32768
#define SMEM_TOTAL (NSTAGE * STG_BYTES) // 98304
#define NRED 16

// ---------------- device scratch ----------------
__device__ __nv_bfloat16 g_Wbf[(size_t)NCLS * EMBED];
__device__ __nv_bfloat16 g_Ebf[(size_t)BATCH * EMBED];
__device__ float g_sumexp[(size_t)NCH * BATCH];
__device__ float g_sumlog[(size_t)NCH * BATCH];
__device__ float g_SE2[(size_t)NRED * BATCH];
__device__ float g_SL2[(size_t)NRED * BATCH];
__device__ float g_labellogit[BATCH];
__device__ float g_part[8];

// ---------------- fp32 -> bf16 ----------------
__global__ void cvt_W(const float4* __restrict__ src) {
    size_t i = (size_t)blockIdx.x * blockDim.x + threadIdx.x;
    size_t n4 = (size_t)NCLS * EMBED / 4;
    if (i < n4) {
        float4 v = src[i];
        __nv_bfloat162* dst = reinterpret_cast<__nv_bfloat162*>(g_Wbf);
        dst[2 * i]     = __float22bfloat162_rn(make_float2(v.x, v.y));
        dst[2 * i + 1] = __float22bfloat162_rn(make_float2(v.z, v.w));
    }
}
__global__ void cvt_E(const float4* __restrict__ src) {
    size_t i = (size_t)blockIdx.x * blockDim.x + threadIdx.x;
    size_t n4 = (size_t)BATCH * EMBED / 4;
    if (i < n4) {
        float4 v = src[i];
        __nv_bfloat162* dst = reinterpret_cast<__nv_bfloat162*>(g_Ebf);
        dst[2 * i]     = __float22bfloat162_rn(make_float2(v.x, v.y));
        dst[2 * i + 1] = __float22bfloat162_rn(make_float2(v.z, v.w));
    }
}

// ---------------- PTX helpers ----------------
__device__ __forceinline__ void ldsm4(uint32_t* r, uint32_t addr) {
    asm volatile("ldmatrix.sync.aligned.m8n8.x4.shared.b16 {%0,%1,%2,%3}, [%4];\n"
                 : "=r"(r[0]), "=r"(r[1]), "=r"(r[2]), "=r"(r[3]) : "r"(addr));
}
__device__ __forceinline__ void mma16816(float* c, const uint32_t* a, uint32_t b0, uint32_t b1) {
    asm volatile("mma.sync.aligned.m16n8k16.row.col.f32.bf16.bf16.f32 "
                 "{%0,%1,%2,%3},{%4,%5,%6,%7},{%8,%9},{%0,%1,%2,%3};\n"
                 : "+f"(c[0]), "+f"(c[1]), "+f"(c[2]), "+f"(c[3])
                 : "r"(a[0]), "r"(a[1]), "r"(a[2]), "r"(a[3]), "r"(b0), "r"(b1));
}
__device__ __forceinline__ void cp16(uint32_t dst, const void* src) {
    asm volatile("cp.async.cg.shared.global [%0], [%1], 16;\n" :: "r"(dst), "l"(src) : "memory");
}
__device__ __forceinline__ void cp16z(uint32_t dst, const void* src, int srcBytes) {
    asm volatile("cp.async.cg.shared.global [%0], [%1], 16, %2;\n"
                 :: "r"(dst), "l"(src), "r"(srcBytes) : "memory");
}

// ---------------- persistent fused GEMM + partial CE ----------------
__global__ __launch_bounds__(256, 2)
void gemm_ce_kernel(const int* __restrict__ labels) {
    extern __shared__ __align__(1024) char dynsm[];
    __shared__ float redSE[2][BM];
    __shared__ float redSL[2][BM];

    const int tid = threadIdx.x;
    const int cta = blockIdx.x;
    const int wid = tid >> 5, lane = tid & 31;
    const int warpM = wid & 3, warpN = wid >> 2;   // 4 x 2 warps -> 32x64 each

    const uint32_t smb = (uint32_t)__cvta_generic_to_shared(dynsm);

    const int nT = (NTILES - cta + NCTA - 1) / NCTA;   // 21 or 22 tiles
    const int G = nT * NKT;                            // total k-steps

    // issue loads for global step gi into stage buffer gi%3
    auto issueG = [&](int gi) {
        const int tile = cta + (gi >> 5) * NCTA;
        const int kt = gi & 31;
        const int rowBase = (tile & (NROWB - 1)) * BM;
        const int cBase = (tile >> 4) * BN;
        const int s = gi % NSTAGE;
        const uint32_t stA = smb + s * STG_BYTES;
        const uint32_t stB = stA + A_BYTES;
        const int kOff = kt * BK;
        const __nv_bfloat16* gA = g_Ebf + (size_t)rowBase * EMBED + kOff;
        #pragma unroll
        for (int i = 0; i < 4; i++) {          // A: 1024 16B chunks / 256 thr
            int idx = tid + i * 256;
            int r = idx >> 3, c = idx & 7;
            cp16(stA + r * 128 + ((c ^ (r & 7)) << 4),
                 gA + (size_t)r * EMBED + c * 8);
        }
        #pragma unroll
        for (int i = 0; i < 4; i++) {          // B
            int idx = tid + i * 256;
            int r = idx >> 3, c = idx & 7;
            int crow = cBase + r;
            int p = (crow < NCLS) ? 16 : 0;
            int cc = (crow < NCLS) ? crow : (NCLS - 1);
            cp16z(stB + r * 128 + ((c ^ (r & 7)) << 4),
                  g_Wbf + (size_t)cc * EMBED + kOff + c * 8, p);
        }
        asm volatile("cp.async.commit_group;\n" ::: "memory");
    };

    float acc[2][8][4];
    #pragma unroll
    for (int mt = 0; mt < 2; mt++)
        #pragma unroll
        for (int nt = 0; nt < 8; nt++)
            #pragma unroll
            for (int v = 0; v < 4; v++) acc[mt][nt][v] = 0.f;

    issueG(0);
    issueG(1);

    int s = 0;   // consume stage = g % 3
    #pragma unroll 1
    for (int g = 0; g < G; g++) {
        asm volatile("cp.async.wait_group 1;\n" ::: "memory");
        __syncthreads();
        {
            int gi = g + 2;
            if (gi < G) issueG(gi);
            else        asm volatile("cp.async.commit_group;\n" ::: "memory");
        }

        const uint32_t aS = smb + s * STG_BYTES;
        const uint32_t bS = aS + A_BYTES;
        s = (s == NSTAGE - 1) ? 0 : s + 1;

        #pragma unroll
        for (int kk = 0; kk < 4; kk++) {
            uint32_t afr[2][4];
            #pragma unroll
            for (int mt = 0; mt < 2; mt++) {
                int row = warpM * 32 + mt * 16 + (lane & 15);
                int kcol = kk * 2 + (lane >> 4);
                ldsm4(afr[mt], aS + row * 128 + ((kcol ^ (row & 7)) << 4));
            }
            uint32_t bfr[4][4];
            #pragma unroll
            for (int ng = 0; ng < 4; ng++) {
                int nrow = warpN * 64 + ng * 16 + ((lane >> 4) << 3) + (lane & 7);
                int kcol = kk * 2 + ((lane >> 3) & 1);
                ldsm4(bfr[ng], bS + nrow * 128 + ((kcol ^ (nrow & 7)) << 4));
            }
            #pragma unroll
            for (int mt = 0; mt < 2; mt++)
                #pragma unroll
                for (int ng = 0; ng < 4; ng++) {
                    mma16816(acc[mt][ng * 2 + 0], afr[mt], bfr[ng][0], bfr[ng][1]);
                    mma16816(acc[mt][ng * 2 + 1], afr[mt], bfr[ng][2], bfr[ng][3]);
                }
        }

        if ((g & 31) == 31) {
            // ---------------- per-tile epilogue (overlaps with prefetched loads) ----------------
            const int tile = cta + (g >> 5) * NCTA;
            const int rowBase = (tile & (NROWB - 1)) * BM;
            const int chunk = tile >> 4;
            const int colBase = chunk * BN + warpN * 64;
            #pragma unroll
            for (int mt = 0; mt < 2; mt++) {
                int rLoc0 = warpM * 32 + mt * 16 + (lane >> 2);
                int rLoc1 = rLoc0 + 8;
                int gr0 = rowBase + rLoc0, gr1 = rowBase + rLoc1;
                int lbl0 = labels[gr0], lbl1 = labels[gr1];
                float se0 = 0.f, sl0 = 0.f, se1 = 0.f, sl1 = 0.f;
                #pragma unroll
                for (int nt = 0; nt < 8; nt++) {
                    int c0 = colBase + nt * 8 + ((lane & 3) << 1);
                    int c1 = c0 + 1;
                    float v00 = acc[mt][nt][0], v01 = acc[mt][nt][1];
                    float v10 = acc[mt][nt][2], v11 = acc[mt][nt][3];
                    if (c0 < NCLS) {
                        se0 += __expf(v00); sl0 += v00;
                        se1 += __expf(v10); sl1 += v10;
                        if (c0 == lbl0) g_labellogit[gr0] = v00;
                        if (c0 == lbl1) g_labellogit[gr1] = v10;
                    }
                    if (c1 < NCLS) {
                        se0 += __expf(v01); sl0 += v01;
                        se1 += __expf(v11); sl1 += v11;
                        if (c1 == lbl0) g_labellogit[gr0] = v01;
                        if (c1 == lbl1) g_labellogit[gr1] = v11;
                    }
                }
                #pragma unroll
                for (int m = 1; m < 4; m <<= 1) {
                    se0 += __shfl_xor_sync(0xffffffffu, se0, m);
                    sl0 += __shfl_xor_sync(0xffffffffu, sl0, m);
                    se1 += __shfl_xor_sync(0xffffffffu, se1, m);
                    sl1 += __shfl_xor_sync(0xffffffffu, sl1, m);
                }
                if ((lane & 3) == 0) {
                    redSE[warpN][rLoc0] = se0; redSL[warpN][rLoc0] = sl0;
                    redSE[warpN][rLoc1] = se1; redSL[warpN][rLoc1] = sl1;
                }
            }
            __syncthreads();
            if (tid < BM) {
                float se = redSE[0][tid] + redSE[1][tid];
                float sl = redSL[0][tid] + redSL[1][tid];
                g_sumexp[(size_t)chunk * BATCH + rowBase + tid] = se;
                g_sumlog[(size_t)chunk * BATCH + rowBase + tid] = sl;
            }
            // reset accumulators for next tile
            #pragma unroll
            for (int mt = 0; mt < 2; mt++)
                #pragma unroll
                for (int nt = 0; nt < 8; nt++)
                    #pragma unroll
                    for (int v = 0; v < 4; v++) acc[mt][nt][v] = 0.f;
        }
    }
}

// ---------------- reductions ----------------
__global__ void reduce1_kernel() {
    int row = blockIdx.x * 256 + threadIdx.x;
    int g = blockIdx.y;
    float S = 0.f, L = 0.f;
    for (int j = g; j < NCH; j += NRED) {
        S += g_sumexp[(size_t)j * BATCH + row];
        L += g_sumlog[(size_t)j * BATCH + row];
    }
    g_SE2[(size_t)g * BATCH + row] = S;
    g_SL2[(size_t)g * BATCH + row] = L;
}

__global__ void reduce2_kernel() {
    int row = blockIdx.x * 256 + threadIdx.x;
    float S = 0.f, L = 0.f;
    #pragma unroll
    for (int g = 0; g < NRED; g++) {
        S += g_SE2[(size_t)g * BATCH + row];
        L += g_SL2[(size_t)g * BATCH + row];
    }
    float per = logf(S) - (1.0f - EPS) * g_labellogit[row] - EPS * (L * (1.0f / (float)NCLS));
    __shared__ float sm[256];
    sm[threadIdx.x] = per;
    __syncthreads();
    for (int s = 128; s > 0; s >>= 1) {
        if (threadIdx.x < s) sm[threadIdx.x] += sm[threadIdx.x + s];
        __syncthreads();
    }
    if (threadIdx.x == 0) g_part[blockIdx.x] = sm[0];
}

__global__ void final_kernel(float* __restrict__ out) {
    if (threadIdx.x == 0) {
        float s = 0.f;
        for (int i = 0; i < 8; i++) s += g_part[i];
        out[0] = s * (1.0f / (float)BATCH);
    }
}

// ---------------- entry ----------------
extern "C" void kernel_launch(void* const* d_in, const int* in_sizes, int n_in,
                              void* d_out, int out_size) {
    const float* E = (const float*)d_in[0];
    const int* labels = (const int*)d_in[1];
    const float* W = (const float*)d_in[2];
    float* out = (float*)d_out;

    static int attr_set = 0;
    if (!attr_set) {
        cudaFuncSetAttribute(gemm_ce_kernel, cudaFuncAttributeMaxDynamicSharedMemorySize,
                             SMEM_TOTAL);
        attr_set = 1;
    }

    size_t nW4 = (size_t)NCLS * EMBED / 4;
    size_t nE4 = (size_t)BATCH * EMBED / 4;
    cvt_W<<<(unsigned)((nW4 + 255) / 256), 256>>>((const float4*)W);
    cvt_E<<<(unsigned)((nE4 + 255) / 256), 256>>>((const float4*)E);

    gemm_ce_kernel<<<NCTA, 256, SMEM_TOTAL>>>(labels);

    dim3 rg(BATCH / 256, NRED);
    reduce1_kernel<<<rg, 256>>>();
    reduce2_kernel<<<BATCH / 256, 256>>>();
    final_kernel<<<1, 32>>>(out);
}

// round 17
// speedup vs baseline: 1.1272x; 1.0550x over previous
#include <cuda_runtime.h>
#include <cuda_bf16.h>
#include <cstdint>

#define BATCH 2048
#define EMBED 2048
#define NCLS  50257
#define EPS   0.1f

#define BM 128
#define BN 128
#define BK 64                      // 64 bf16 = 128B row (one swizzle phase)
#define NKT (EMBED / BK)           // 32
#define NCH ((NCLS + BN - 1) / BN) // 393
#define NSTAGE 3
#define A_BYTES (BM * BK * 2)      // 16384
#define B_BYTES (BN * BK * 2)      // 16384
#define STG_BYTES (A_BYTES + B_BYTES)           // 32768
#define SMEM_TOTAL (NSTAGE * STG_BYTES)         // 98304
#define NRED 16

// ---------------- device scratch ----------------
__device__ __nv_bfloat16 g_Wbf[(size_t)NCLS * EMBED];
__device__ __nv_bfloat16 g_Ebf[(size_t)BATCH * EMBED];
__device__ float g_sumexp[(size_t)NCH * BATCH];
__device__ float g_sumlog[(size_t)NCH * BATCH];
__device__ float g_SE2[(size_t)NRED * BATCH];
__device__ float g_SL2[(size_t)NRED * BATCH];
__device__ float g_labellogit[BATCH];
__device__ float g_part[8];

// ---------------- fp32 -> bf16 (W and E in one launch) ----------------
#define NW4 ((size_t)NCLS * EMBED / 4)
#define NE4 ((size_t)BATCH * EMBED / 4)
__global__ void cvt_all(const float4* __restrict__ srcW, const float4* __restrict__ srcE) {
    size_t i = (size_t)blockIdx.x * blockDim.x + threadIdx.x;
    if (i < NW4) {
        float4 v = srcW[i];
        __nv_bfloat162* dst = reinterpret_cast<__nv_bfloat162*>(g_Wbf);
        dst[2 * i]     = __float22bfloat162_rn(make_float2(v.x, v.y));
        dst[2 * i + 1] = __float22bfloat162_rn(make_float2(v.z, v.w));
    } else if (i - NW4 < NE4) {
        size_t j = i - NW4;
        float4 v = srcE[j];
        __nv_bfloat162* dst = reinterpret_cast<__nv_bfloat162*>(g_Ebf);
        dst[2 * j]     = __float22bfloat162_rn(make_float2(v.x, v.y));
        dst[2 * j + 1] = __float22bfloat162_rn(make_float2(v.z, v.w));
    }
}

// ---------------- PTX helpers ----------------
__device__ __forceinline__ void ldsm4(uint32_t* r, uint32_t addr) {
    asm volatile("ldmatrix.sync.aligned.m8n8.x4.shared.b16 {%0,%1,%2,%3}, [%4];\n"
                 : "=r"(r[0]), "=r"(r[1]), "=r"(r[2]), "=r"(r[3]) : "r"(addr));
}
__device__ __forceinline__ void mma16816(float* c, const uint32_t* a, uint32_t b0, uint32_t b1) {
    asm volatile("mma.sync.aligned.m16n8k16.row.col.f32.bf16.bf16.f32 "
                 "{%0,%1,%2,%3},{%4,%5,%6,%7},{%8,%9},{%0,%1,%2,%3};\n"
                 : "+f"(c[0]), "+f"(c[1]), "+f"(c[2]), "+f"(c[3])
                 : "r"(a[0]), "r"(a[1]), "r"(a[2]), "r"(a[3]), "r"(b0), "r"(b1));
}
__device__ __forceinline__ void cp16(uint32_t dst, const void* src) {
    asm volatile("cp.async.cg.shared.global [%0], [%1], 16;\n" :: "r"(dst), "l"(src) : "memory");
}
__device__ __forceinline__ void cp16z(uint32_t dst, const void* src, int srcBytes) {
    asm volatile("cp.async.cg.shared.global [%0], [%1], 16, %2;\n"
                 :: "r"(dst), "l"(src), "r"(srcBytes) : "memory");
}

// ---------------- fused GEMM + partial CE (R7 configuration) ----------------
__global__ __launch_bounds__(256, 2)
void gemm_ce_kernel(const int* __restrict__ labels) {
    extern __shared__ __align__(1024) char dynsm[];
    __shared__ float redSE[2][BM];
    __shared__ float redSL[2][BM];

    const int tid = threadIdx.x;
    const int rowBase = blockIdx.x * BM;   // x = rowblock (fast) -> wave shares W chunk
    const int chunk = blockIdx.y;          // y = class chunk
    const int cBase = chunk * BN;
    const int wid = tid >> 5, lane = tid & 31;
    const int warpM = wid & 3, warpN = wid >> 2;   // 4 x 2 warps -> 32x64 each

    const uint32_t smb = (uint32_t)__cvta_generic_to_shared(dynsm);
    const __nv_bfloat16* gA = g_Ebf + (size_t)rowBase * EMBED;

    auto issueStage = [&](int kt) {
        const int s = kt % NSTAGE;
        const uint32_t stA = smb + s * STG_BYTES;
        const uint32_t stB = stA + A_BYTES;
        const int kOff = kt * BK;
        #pragma unroll
        for (int i = 0; i < 4; i++) {          // A: 1024 16B chunks / 256 thr
            int idx = tid + i * 256;
            int r = idx >> 3, c = idx & 7;
            cp16(stA + r * 128 + ((c ^ (r & 7)) << 4),
                 gA + (size_t)r * EMBED + kOff + c * 8);
        }
        #pragma unroll
        for (int i = 0; i < 4; i++) {          // B
            int idx = tid + i * 256;
            int r = idx >> 3, c = idx & 7;
            int crow = cBase + r;
            int p = (crow < NCLS) ? 16 : 0;
            int cc = (crow < NCLS) ? crow : (NCLS - 1);
            cp16z(stB + r * 128 + ((c ^ (r & 7)) << 4),
                  g_Wbf + (size_t)cc * EMBED + kOff + c * 8, p);
        }
        asm volatile("cp.async.commit_group;\n" ::: "memory");
    };

    float acc[2][8][4];
    #pragma unroll
    for (int mt = 0; mt < 2; mt++)
        #pragma unroll
        for (int nt = 0; nt < 8; nt++)
            #pragma unroll
            for (int v = 0; v < 4; v++) acc[mt][nt][v] = 0.f;

    issueStage(0);
    issueStage(1);

    #pragma unroll 1
    for (int kt = 0; kt < NKT; kt++) {
        if (kt < NKT - 2) asm volatile("cp.async.wait_group 1;\n" ::: "memory");
        else              asm volatile("cp.async.wait_group 0;\n" ::: "memory");
        __syncthreads();
        if (kt + 2 < NKT) issueStage(kt + 2);

        const int s = kt % NSTAGE;
        const uint32_t aS = smb + s * STG_BYTES;
        const uint32_t bS = aS + A_BYTES;

        #pragma unroll
        for (int kk = 0; kk < 4; kk++) {
            uint32_t afr[2][4];
            #pragma unroll
            for (int mt = 0; mt < 2; mt++) {
                int row = warpM * 32 + mt * 16 + (lane & 15);
                int kcol = kk * 2 + (lane >> 4);
                ldsm4(afr[mt], aS + row * 128 + ((kcol ^ (row & 7)) << 4));
            }
            uint32_t bfr[4][4];
            #pragma unroll
            for (int ng = 0; ng < 4; ng++) {
                int nrow = warpN * 64 + ng * 16 + ((lane >> 4) << 3) + (lane & 7);
                int kcol = kk * 2 + ((lane >> 3) & 1);
                ldsm4(bfr[ng], bS + nrow * 128 + ((kcol ^ (nrow & 7)) << 4));
            }
            #pragma unroll
            for (int mt = 0; mt < 2; mt++)
                #pragma unroll
                for (int ng = 0; ng < 4; ng++) {
                    mma16816(acc[mt][ng * 2 + 0], afr[mt], bfr[ng][0], bfr[ng][1]);
                    mma16816(acc[mt][ng * 2 + 1], afr[mt], bfr[ng][2], bfr[ng][3]);
                }
        }
    }
    __syncthreads();

    // ---------------- fused epilogue ----------------
    const int colBase = cBase + warpN * 64;
    const int rL0 = warpM * 32 + (lane >> 2);
    const int lblA = labels[rowBase + rL0];
    const int lblB = labels[rowBase + rL0 + 8];
    const int lblC = labels[rowBase + rL0 + 16];
    const int lblD = labels[rowBase + rL0 + 24];
    #pragma unroll
    for (int mt = 0; mt < 2; mt++) {
        int rLoc0 = rL0 + mt * 16;
        int rLoc1 = rLoc0 + 8;
        int gr0 = rowBase + rLoc0, gr1 = rowBase + rLoc1;
        int lbl0 = mt ? lblC : lblA;
        int lbl1 = mt ? lblD : lblB;
        float se0 = 0.f, sl0 = 0.f, se1 = 0.f, sl1 = 0.f;
        #pragma unroll
        for (int nt = 0; nt < 8; nt++) {
            int c0 = colBase + nt * 8 + ((lane & 3) << 1);
            int c1 = c0 + 1;
            float v00 = acc[mt][nt][0], v01 = acc[mt][nt][1];
            float v10 = acc[mt][nt][2], v11 = acc[mt][nt][3];
            if (c0 < NCLS) {
                se0 += __expf(v00); sl0 += v00;
                se1 += __expf(v10); sl1 += v10;
                if (c0 == lbl0) g_labellogit[gr0] = v00;
                if (c0 == lbl1) g_labellogit[gr1] = v10;
            }
            if (c1 < NCLS) {
                se0 += __expf(v01); sl0 += v01;
                se1 += __expf(v11); sl1 += v11;
                if (c1 == lbl0) g_labellogit[gr0] = v01;
                if (c1 == lbl1) g_labellogit[gr1] = v11;
            }
        }
        #pragma unroll
        for (int m = 1; m < 4; m <<= 1) {
            se0 += __shfl_xor_sync(0xffffffffu, se0, m);
            sl0 += __shfl_xor_sync(0xffffffffu, sl0, m);
            se1 += __shfl_xor_sync(0xffffffffu, se1, m);
            sl1 += __shfl_xor_sync(0xffffffffu, sl1, m);
        }
        if ((lane & 3) == 0) {
            redSE[warpN][rLoc0] = se0; redSL[warpN][rLoc0] = sl0;
            redSE[warpN][rLoc1] = se1; redSL[warpN][rLoc1] = sl1;
        }
    }
    __syncthreads();
    if (tid < BM) {
        float se = redSE[0][tid] + redSE[1][tid];
        float sl = redSL[0][tid] + redSL[1][tid];
        g_sumexp[(size_t)chunk * BATCH + rowBase + tid] = se;
        g_sumlog[(size_t)chunk * BATCH + rowBase + tid] = sl;
    }
}

// ---------------- reductions ----------------
__global__ void reduce1_kernel() {
    int row = blockIdx.x * 256 + threadIdx.x;
    int g = blockIdx.y;
    float S = 0.f, L = 0.f;
    for (int j = g; j < NCH; j += NRED) {
        S += g_sumexp[(size_t)j * BATCH + row];
        L += g_sumlog[(size_t)j * BATCH + row];
    }
    g_SE2[(size_t)g * BATCH + row] = S;
    g_SL2[(size_t)g * BATCH + row] = L;
}

__global__ void reduce2_kernel() {
    int row = blockIdx.x * 256 + threadIdx.x;
    float S = 0.f, L = 0.f;
    #pragma unroll
    for (int g = 0; g < NRED; g++) {
        S += g_SE2[(size_t)g * BATCH + row];
        L += g_SL2[(size_t)g * BATCH + row];
    }
    float per = logf(S) - (1.0f - EPS) * g_labellogit[row] - EPS * (L * (1.0f / (float)NCLS));
    __shared__ float sm[256];
    sm[threadIdx.x] = per;
    __syncthreads();
    for (int s = 128; s > 0; s >>= 1) {
        if (threadIdx.x < s) sm[threadIdx.x] += sm[threadIdx.x + s];
        __syncthreads();
    }
    if (threadIdx.x == 0) g_part[blockIdx.x] = sm[0];
}

__global__ void final_kernel(float* __restrict__ out) {
    if (threadIdx.x == 0) {
        float s = 0.f;
        for (int i = 0; i < 8; i++) s += g_part[i];
        out[0] = s * (1.0f / (float)BATCH);
    }
}

// ---------------- entry ----------------
extern "C" void kernel_launch(void* const* d_in, const int* in_sizes, int n_in,
                              void* d_out, int out_size) {
    const float* E = (const float*)d_in[0];
    const int* labels = (const int*)d_in[1];
    const float* W = (const float*)d_in[2];
    float* out = (float*)d_out;

    static int attr_set = 0;
    if (!attr_set) {
        cudaFuncSetAttribute(gemm_ce_kernel, cudaFuncAttributeMaxDynamicSharedMemorySize,
                             SMEM_TOTAL);
        attr_set = 1;
    }

    size_t nAll = NW4 + NE4;
    cvt_all<<<(unsigned)((nAll + 255) / 256), 256>>>((const float4*)W, (const float4*)E);

    dim3 grid(BATCH / BM, NCH);   // 16 x 393 ; x fast -> wave shares W chunk via L2
    gemm_ce_kernel<<<grid, 256, SMEM_TOTAL>>>(labels);

    dim3 rg(BATCH / 256, NRED);
    reduce1_kernel<<<rg, 256>>>();
    reduce2_kernel<<<BATCH / 256, 256>>>();
    final_kernel<<<1, 32>>>(out);
}